// round 1
// baseline (speedup 1.0000x reference)
#include <cuda_runtime.h>
#include <cuda_bf16.h>
#include <math.h>

#define Lc   1024
#define Bc   2
#define Dc   1024
#define Hc   16
#define DHc  64
#define DFFc 4096
#define MEMc 1024
#define Tc   2048
#define HDc  (Hc*DHc)          // 1024
#define SCALEF 0.125f

// ---------------- scratch (device globals; no allocation) ----------------
__device__ float g_c   [Tc*Bc*Dc];          // concat(memory, x)      [T,B,D]
__device__ float g_kv  [Tc*Bc*2*HDc];       // kv proj                [T,B,2*H*DH]
__device__ float g_r   [Tc*Bc*HDc];         // rel proj               [T,B,H*DH]
__device__ float g_q   [Lc*Bc*HDc];         // q proj                 [L,B,H*DH]
__device__ float g_AC  [67108864];          // [B*H, L, T] scores AC, then probs (in place)
__device__ float g_BD  [67108864];          // [B*H, L, T] scores BD (unshifted)
__device__ float g_vec [Lc*Bc*HDc];         // attention output vec   [L,B,H*DH]
__device__ float g_res [Lc*Bc*Dc];          // x + attn_out
__device__ float g_out1[Lc*Bc*Dc];          // ln1 output
__device__ float g_ff1 [Lc*Bc*DFFc];        // relu(out1@W1+b1)
__device__ float g_res2[Lc*Bc*Dc];          // out1 + ff

// ---------------- concat(memory, x) -> c ----------------
__global__ void concat_kernel(const float* __restrict__ mem, const float* __restrict__ x,
                              float* __restrict__ c) {
    int idx = blockIdx.x * 256 + threadIdx.x;
    if (idx < Tc*Bc*Dc)
        c[idx] = (idx < MEMc*Bc*Dc) ? mem[idx] : x[idx - MEMc*Bc*Dc];
}

// ---------------- generic batched SGEMM: C = A*B (+bias)(+resid)(relu) ----------------
// 128x128 tile, 8x8 per thread, K step 8. Batch z decodes to (b,h)=(z/Hdim, z%Hdim)
// with independent (b,h) strides for A, B, C.
__global__ __launch_bounds__(256)
void sgemm_kernel(const float* __restrict__ A, const float* __restrict__ B,
                  float* __restrict__ C,
                  int M, int N, int K, int lda, int ldb, int ldc,
                  int Hdim, long long sAb, long long sAh, long long sBb, long long sBh,
                  long long sCb, long long sCh,
                  const float* __restrict__ bias, const float* __restrict__ resid,
                  int ldr, int doRelu)
{
    int z  = blockIdx.z;
    int bz = z / Hdim, hz = z % Hdim;
    A += bz * sAb + hz * sAh;
    B += bz * sBb + hz * sBh;
    C += bz * sCb + hz * sCh;

    __shared__ float As[8][128];
    __shared__ float Bs[8][128];

    int tid = threadIdx.x;
    int bm = blockIdx.y * 128, bn = blockIdx.x * 128;

    int arow = tid >> 1;            // 0..127
    int ak   = (tid & 1) * 4;       // 0 or 4
    int bkr  = tid >> 5;            // 0..7
    int bcol = (tid & 31) * 4;      // 0..124
    int mt   = (tid >> 4) * 8;
    int nt   = (tid & 15) * 8;

    float acc[8][8];
#pragma unroll
    for (int i = 0; i < 8; i++)
#pragma unroll
        for (int j = 0; j < 8; j++) acc[i][j] = 0.f;

    for (int k0 = 0; k0 < K; k0 += 8) {
        float4 av = make_float4(0.f,0.f,0.f,0.f);
        if (bm + arow < M)
            av = *(const float4*)(A + (size_t)(bm + arow) * lda + k0 + ak);
        As[ak+0][arow] = av.x; As[ak+1][arow] = av.y;
        As[ak+2][arow] = av.z; As[ak+3][arow] = av.w;

        float4 bv = make_float4(0.f,0.f,0.f,0.f);
        if (bn + bcol < N)
            bv = *(const float4*)(B + (size_t)(k0 + bkr) * ldb + bn + bcol);
        *(float4*)&Bs[bkr][bcol] = bv;
        __syncthreads();

#pragma unroll
        for (int kk = 0; kk < 8; kk++) {
            float a[8], b[8];
            *(float4*)(a)   = *(float4*)&As[kk][mt];
            *(float4*)(a+4) = *(float4*)&As[kk][mt+4];
            *(float4*)(b)   = *(float4*)&Bs[kk][nt];
            *(float4*)(b+4) = *(float4*)&Bs[kk][nt+4];
#pragma unroll
            for (int i = 0; i < 8; i++)
#pragma unroll
                for (int j = 0; j < 8; j++) acc[i][j] += a[i]*b[j];
        }
        __syncthreads();
    }

#pragma unroll
    for (int i = 0; i < 8; i++) {
        int m = bm + mt + i;
        if (m >= M) continue;
#pragma unroll
        for (int j = 0; j < 8; j++) {
            int n = bn + nt + j;
            if (n >= N) continue;
            float v = acc[i][j];
            if (bias)  v += bias[n];
            if (resid) v += resid[(size_t)m * ldr + n];
            if (doRelu) v = fmaxf(v, 0.f);
            C[(size_t)m * ldc + n] = v;
        }
    }
}

// ---------------- score GEMM: Out[z,i,j] = sum_d (Q[i]+bias)[d] * Kmat[j][d] ----------------
// 64x64 tile, K=DH=64 in one shot. z = b*H + h.
__global__ __launch_bounds__(256)
void score_kernel(const float* __restrict__ Q, const float* __restrict__ Km,
                  const float* __restrict__ bias, float* __restrict__ Out,
                  int kRow, long long sKb, long long sKh)
{
    __shared__ float Qs[64][68];   // [d][m]
    __shared__ float Ks[64][68];   // [d][n]
    int tid = threadIdx.x;
    int z = blockIdx.z;
    int b = z / Hc, h = z % Hc;
    const float* q  = Q + (size_t)z * DHc;                 // row stride B*H*DH = 2048
    const float* kp = Km + (size_t)b * sKb + (size_t)h * sKh;
    const float* bi = bias + h * DHc;
    int i0 = blockIdx.y * 64, j0 = blockIdx.x * 64;

    for (int it = tid; it < 64*16; it += 256) {
        int row = it >> 4, d4 = (it & 15) << 2;
        float4 v = *(const float4*)(q + (size_t)(i0 + row) * (Bc*HDc) + d4);
        Qs[d4+0][row] = v.x + bi[d4+0];
        Qs[d4+1][row] = v.y + bi[d4+1];
        Qs[d4+2][row] = v.z + bi[d4+2];
        Qs[d4+3][row] = v.w + bi[d4+3];
    }
    for (int it = tid; it < 64*16; it += 256) {
        int row = it >> 4, d4 = (it & 15) << 2;
        float4 v = *(const float4*)(kp + (size_t)(j0 + row) * kRow + d4);
        Ks[d4+0][row] = v.x; Ks[d4+1][row] = v.y;
        Ks[d4+2][row] = v.z; Ks[d4+3][row] = v.w;
    }
    __syncthreads();

    int mt = (tid >> 4) * 4, nt = (tid & 15) * 4;
    float acc[4][4];
#pragma unroll
    for (int i = 0; i < 4; i++)
#pragma unroll
        for (int j = 0; j < 4; j++) acc[i][j] = 0.f;

#pragma unroll
    for (int d = 0; d < 64; d++) {
        float4 qa = *(const float4*)&Qs[d][mt];
        float4 kb = *(const float4*)&Ks[d][nt];
        float a[4] = {qa.x, qa.y, qa.z, qa.w};
        float c[4] = {kb.x, kb.y, kb.z, kb.w};
#pragma unroll
        for (int i = 0; i < 4; i++)
#pragma unroll
            for (int j = 0; j < 4; j++) acc[i][j] += a[i]*c[j];
    }

#pragma unroll
    for (int i = 0; i < 4; i++) {
        float* op = Out + ((size_t)z * Lc + i0 + mt + i) * Tc + j0 + nt;
#pragma unroll
        for (int j = 0; j < 4; j++) op[j] = acc[i][j];
    }
}

// ---------------- masked softmax with analytic rel-shift, in place over AC ----------------
__global__ __launch_bounds__(256)
void softmax_kernel(float* __restrict__ P, const float* __restrict__ BD)
{
    int i = blockIdx.x, z = blockIdx.y;
    float*       ac = P  + ((size_t)z * Lc + i) * Tc;
    const float* bd = BD + ((size_t)z * Lc + i) * Tc;
    int valid = i + MEMc + 1;           // <= T
    int shift = Lc - 1 - i;             // BD_shift[i,j] = BD[i, j+shift]
    __shared__ float red[256];
    int tid = threadIdx.x;

    float mx = -1e30f;
    for (int j = tid; j < valid; j += 256)
        mx = fmaxf(mx, (ac[j] + bd[j + shift]) * SCALEF);
    red[tid] = mx; __syncthreads();
    for (int s = 128; s > 0; s >>= 1) {
        if (tid < s) red[tid] = fmaxf(red[tid], red[tid + s]);
        __syncthreads();
    }
    mx = red[0]; __syncthreads();

    float sum = 0.f;
    for (int j = tid; j < valid; j += 256)
        sum += __expf((ac[j] + bd[j + shift]) * SCALEF - mx);
    red[tid] = sum; __syncthreads();
    for (int s = 128; s > 0; s >>= 1) {
        if (tid < s) red[tid] += red[tid + s];
        __syncthreads();
    }
    float inv = 1.f / red[0];

    for (int j = tid; j < Tc; j += 256) {
        float p = 0.f;
        if (j < valid)
            p = __expf((ac[j] + bd[j + shift]) * SCALEF - mx) * inv;
        ac[j] = p;
    }
}

// ---------------- attn_matrix = mean over (b,h) of prob ----------------
__global__ __launch_bounds__(256)
void attn_reduce_kernel(const float* __restrict__ P, float* __restrict__ attn)
{
    int i = blockIdx.x;
    for (int j = threadIdx.x; j < Tc; j += 256) {
        float s = 0.f;
#pragma unroll
        for (int z = 0; z < Bc*Hc; z++)
            s += P[((size_t)z * Lc + i) * Tc + j];
        attn[(size_t)i * Tc + j] = s * (1.f / (Bc*Hc));
    }
}

// ---------------- layernorm over last dim D ----------------
__global__ __launch_bounds__(256)
void ln_kernel(const float* __restrict__ X, float* __restrict__ Y,
               const float* __restrict__ g, const float* __restrict__ b)
{
    int row = blockIdx.x;
    const float* xr = X + (size_t)row * Dc;
    float*       yr = Y + (size_t)row * Dc;
    __shared__ float r1[256], r2[256];
    int tid = threadIdx.x;
    float s1 = 0.f, s2 = 0.f;
    for (int d = tid; d < Dc; d += 256) {
        float v = xr[d];
        s1 += v; s2 += v*v;
    }
    r1[tid] = s1; r2[tid] = s2; __syncthreads();
    for (int s = 128; s > 0; s >>= 1) {
        if (tid < s) { r1[tid] += r1[tid+s]; r2[tid] += r2[tid+s]; }
        __syncthreads();
    }
    float mean = r1[0] * (1.f/Dc);
    float var  = r2[0] * (1.f/Dc) - mean*mean;
    float rinv = rsqrtf(var + 1e-5f);
    for (int d = tid; d < Dc; d += 256)
        yr[d] = (xr[d] - mean) * rinv * g[d] + b[d];
}

// ---------------- host ----------------
static void launch_gemm(const float* A, const float* B, float* C,
                        int M, int N, int K, int lda, int ldb, int ldc,
                        int Z, int Hdim,
                        long long sAb, long long sAh, long long sBb, long long sBh,
                        long long sCb, long long sCh,
                        const float* bias, const float* resid, int ldr, int doRelu)
{
    dim3 g((N + 127) / 128, (M + 127) / 128, Z);
    sgemm_kernel<<<g, 256>>>(A, B, C, M, N, K, lda, ldb, ldc, Hdim,
                             sAb, sAh, sBb, sBh, sCb, sCh, bias, resid, ldr, doRelu);
}

extern "C" void kernel_launch(void* const* d_in, const int* in_sizes, int n_in,
                              void* d_out, int out_size)
{
    // Resolve input ordering: dict order has Wq (1048576) at index 5,
    // signature order has mask (4194304) at index 5.
    int o = (in_sizes[5] == 1048576) ? 0 : 1;

    const float* x    = (const float*)d_in[0];
    const float* pe   = (const float*)d_in[1];
    const float* pu   = (const float*)d_in[2];
    const float* pv   = (const float*)d_in[3];
    const float* mem  = (const float*)d_in[4];
    const float* Wq   = (const float*)d_in[5  + o];
    const float* Wkv  = (const float*)d_in[6  + o];
    const float* Wo   = (const float*)d_in[7  + o];
    const float* Wrel = (const float*)d_in[8  + o];
    const float* g1   = (const float*)d_in[9  + o];
    const float* b1l  = (const float*)d_in[10 + o];
    const float* W1   = (const float*)d_in[11 + o];
    const float* b1   = (const float*)d_in[12 + o];
    const float* W2   = (const float*)d_in[13 + o];
    const float* b2   = (const float*)d_in[14 + o];
    const float* g2   = (const float*)d_in[15 + o];
    const float* b2l  = (const float*)d_in[16 + o];

    float *p_c, *p_kv, *p_r, *p_q, *p_AC, *p_BD, *p_vec, *p_res, *p_out1, *p_ff1, *p_res2;
    cudaGetSymbolAddress((void**)&p_c,    g_c);
    cudaGetSymbolAddress((void**)&p_kv,   g_kv);
    cudaGetSymbolAddress((void**)&p_r,    g_r);
    cudaGetSymbolAddress((void**)&p_q,    g_q);
    cudaGetSymbolAddress((void**)&p_AC,   g_AC);
    cudaGetSymbolAddress((void**)&p_BD,   g_BD);
    cudaGetSymbolAddress((void**)&p_vec,  g_vec);
    cudaGetSymbolAddress((void**)&p_res,  g_res);
    cudaGetSymbolAddress((void**)&p_out1, g_out1);
    cudaGetSymbolAddress((void**)&p_ff1,  g_ff1);
    cudaGetSymbolAddress((void**)&p_res2, g_res2);

    float* out_main = (float*)d_out;                      // [L,B,D]
    float* out_attn = out_main + (size_t)Lc*Bc*Dc;        // [L,T]

    // 1) c = concat(memory, x)
    concat_kernel<<<(Tc*Bc*Dc + 255)/256, 256>>>(mem, x, p_c);

    // 2) kv = c @ Wkv   [T*B, 2*H*DH]
    launch_gemm(p_c, Wkv, p_kv, Tc*Bc, 2*HDc, Dc, Dc, 2*HDc, 2*HDc,
                1, 1, 0,0,0,0,0,0, nullptr, nullptr, 0, 0);
    // 3) r = pos_emb @ Wrel   [T*B, H*DH]
    launch_gemm(pe, Wrel, p_r, Tc*Bc, HDc, Dc, Dc, HDc, HDc,
                1, 1, 0,0,0,0,0,0, nullptr, nullptr, 0, 0);
    // 4) q = x @ Wq   [L*B, H*DH]
    launch_gemm(x, Wq, p_q, Lc*Bc, HDc, Dc, Dc, HDc, HDc,
                1, 1, 0,0,0,0,0,0, nullptr, nullptr, 0, 0);

    // 5) AC[z,i,j] = (q+u)·k ;  BD[z,i,j] = (q+v)·r   (unshifted)
    dim3 sg(Tc/64, Lc/64, Bc*Hc);
    score_kernel<<<sg, 256>>>(p_q, p_kv, pu, p_AC,
                              /*kRow*/ Bc*2*HDc, /*sKb*/ (long long)2*HDc, /*sKh*/ DHc);
    score_kernel<<<sg, 256>>>(p_q, p_r,  pv, p_BD,
                              /*kRow*/ Bc*HDc,   /*sKb*/ (long long)HDc,   /*sKh*/ DHc);

    // 6) masked softmax (rel-shift folded in), probs in place over AC
    softmax_kernel<<<dim3(Lc, Bc*Hc), 256>>>(p_AC, p_BD);

    // 7) attn_matrix = mean over (b,h)
    attn_reduce_kernel<<<Lc, 256>>>(p_AC, out_attn);

    // 8) vec[z] = prob[z] @ v[z]   (M=L, N=DH, K=T), batched over z=(b,h)
    launch_gemm(p_AC, p_kv + HDc, p_vec, Lc, DHc, Tc, Tc, Bc*2*HDc, Bc*HDc,
                Bc*Hc, Hc,
                (long long)Hc*Lc*Tc, (long long)Lc*Tc,   // A (prob) strides
                (long long)2*HDc, DHc,                   // B (v) strides
                (long long)HDc, DHc,                     // C (vec) strides
                nullptr, nullptr, 0, 0);

    // 9) res = x + vec @ Wo
    launch_gemm(p_vec, Wo, p_res, Lc*Bc, Dc, HDc, HDc, Dc, Dc,
                1, 1, 0,0,0,0,0,0, nullptr, x, Dc, 0);

    // 10) out1 = LN1(res)
    ln_kernel<<<Lc*Bc, 256>>>(p_res, p_out1, g1, b1l);

    // 11) ff1 = relu(out1 @ W1 + b1)
    launch_gemm(p_out1, W1, p_ff1, Lc*Bc, DFFc, Dc, Dc, DFFc, DFFc,
                1, 1, 0,0,0,0,0,0, b1, nullptr, 0, 1);

    // 12) res2 = out1 + ff1 @ W2 + b2
    launch_gemm(p_ff1, W2, p_res2, Lc*Bc, Dc, DFFc, DFFc, Dc, Dc,
                1, 1, 0,0,0,0,0,0, b2, p_out1, Dc, 0);

    // 13) out = LN2(res2)  -> d_out region 1
    ln_kernel<<<Lc*Bc, 256>>>(p_res2, out_main, g2, b2l);
}

// round 2
// speedup vs baseline: 2.7184x; 2.7184x over previous
#include <cuda_runtime.h>
#include <cuda_bf16.h>
#include <math.h>

#define Lc   1024
#define Bc   2
#define Dc   1024
#define Hc   16
#define DHc  64
#define DFFc 4096
#define MEMc 1024
#define Tc   2048
#define HDc  (Hc*DHc)          // 1024
#define SCALEF 0.125f

// ---------------- scratch (device globals; no allocation) ----------------
__device__ float g_c   [Tc*Bc*Dc];
__device__ float g_kv  [Tc*Bc*2*HDc];
__device__ float g_r   [Tc*Bc*HDc];
__device__ float g_q   [Lc*Bc*HDc];
__device__ float g_qu  [Lc*Bc*HDc];
__device__ float g_qv  [Lc*Bc*HDc];
__device__ float g_AC  [67108864];          // [B*H, L, T] scores AC, then probs (in place)
__device__ float g_BD  [67108864];          // [B*H, L, T] scores BD (unshifted)
__device__ float g_vec [Lc*Bc*HDc];
__device__ float g_res [Lc*Bc*Dc];
__device__ float g_out1[Lc*Bc*Dc];
__device__ float g_ff1 [Lc*Bc*DFFc];
__device__ float g_res2[Lc*Bc*Dc];

// ---------------- small helpers ----------------
__device__ __forceinline__ unsigned f2tf32(float f) {
    unsigned u;
    asm("cvt.rna.tf32.f32 %0, %1;" : "=r"(u) : "f"(f));
    return u;
}
__device__ __forceinline__ void mma_tf32(float c[4], const unsigned a[4], const unsigned b[2]) {
    asm volatile(
        "mma.sync.aligned.m16n8k8.row.col.f32.tf32.tf32.f32 "
        "{%0,%1,%2,%3}, {%4,%5,%6,%7}, {%8,%9}, {%0,%1,%2,%3};"
        : "+f"(c[0]), "+f"(c[1]), "+f"(c[2]), "+f"(c[3])
        : "r"(a[0]), "r"(a[1]), "r"(a[2]), "r"(a[3]), "r"(b[0]), "r"(b[1]));
}
__device__ __forceinline__ void cp16(void* smem, const void* gmem, int pred) {
    unsigned s = (unsigned)__cvta_generic_to_shared(smem);
    int sz = pred ? 16 : 0;
    asm volatile("cp.async.ca.shared.global [%0], [%1], 16, %2;" :: "r"(s), "l"(gmem), "r"(sz));
}
__device__ __forceinline__ void cp_commit() { asm volatile("cp.async.commit_group;"); }
__device__ __forceinline__ void cp_wait1() { asm volatile("cp.async.wait_group 1;"); }
__device__ __forceinline__ void cp_wait0() { asm volatile("cp.async.wait_group 0;"); }

// ---------------- concat(memory, x) -> c ----------------
__global__ void concat_kernel(const float* __restrict__ mem, const float* __restrict__ x,
                              float* __restrict__ c) {
    int idx = blockIdx.x * 256 + threadIdx.x;
    if (idx < Tc*Bc*Dc)
        c[idx] = (idx < MEMc*Bc*Dc) ? mem[idx] : x[idx - MEMc*Bc*Dc];
}

// ---------------- qu = q + u[h], qv = q + v[h] ----------------
__global__ void qbias_kernel(const float* __restrict__ q, const float* __restrict__ u,
                             const float* __restrict__ v,
                             float* __restrict__ qu, float* __restrict__ qv) {
    int idx = blockIdx.x * 256 + threadIdx.x;
    if (idx < Lc*Bc*HDc) {
        int hd = idx & (HDc - 1);          // h*64+d
        float val = q[idx];
        qu[idx] = val + u[hd];
        qv[idx] = val + v[hd];
    }
}

// ---------------- TF32 tensor-core GEMM ----------------
// C = A * B (+bias)(+resid)(relu). A row-major [M,K] (lda). If !transB, B row-major
// [K,N] (ldb). If transB, B row-major [N,K] (ldb) and C = A*B^T.
// Requirements: M % 128 == 0, K % 16 == 0. N guarded.
// Batch z decodes (b,h) = (z/Hdim, z%Hdim) with independent strides.
#define AS_(s,m,k)  As[(s)][(m)*20 + (k)]
#define BSN_(s,k,n) Bs[(s)][(k)*136 + (n)]
#define BST_(s,n,k) Bs[(s)][(n)*20 + (k)]

__global__ __launch_bounds__(256, 2)
void tf32_gemm(const float* __restrict__ A, const float* __restrict__ B,
               float* __restrict__ C,
               int M, int N, int K, int lda, int ldb, int ldc,
               int Hdim, long long sAb, long long sAh, long long sBb, long long sBh,
               long long sCb, long long sCh,
               const float* __restrict__ bias, const float* __restrict__ resid,
               int ldr, int doRelu, int transB)
{
    __shared__ float As[2][128*20];
    __shared__ float Bs[2][2560];

    int z  = blockIdx.z;
    int bz = z / Hdim, hz = z % Hdim;
    A += bz * sAb + hz * sAh;
    B += bz * sBb + hz * sBh;
    C += bz * sCb + hz * sCh;

    int tid  = threadIdx.x;
    int lane = tid & 31, warp = tid >> 5;
    int qid  = lane >> 2, tq = lane & 3;
    int wm   = (warp >> 2) * 64;           // 0 or 64
    int wn   = (warp & 3) * 32;            // 0,32,64,96
    int bm   = blockIdx.y * 128, bn = blockIdx.x * 128;

    int nk = K >> 4;

    // ---- stage loader ----
    auto load_stage = [&](int s, int k0) {
#pragma unroll
        for (int i = 0; i < 2; i++) {
            int c = tid + i * 256;                 // 0..511
            {   // A chunk: m = c>>2, kq = c&3
                int m = c >> 2, kq = c & 3;
                cp16(&AS_(s, m, kq*4), A + (size_t)(bm + m) * lda + k0 + kq*4, 1);
            }
            if (transB) {                          // B tile [128 n][16 k]
                int n = c >> 2, kq = c & 3;
                int ok = (bn + n) < N;
                cp16(&BST_(s, n, kq*4), B + (size_t)(bn + n) * ldb + k0 + kq*4, ok);
            } else {                               // B tile [16 k][128 n]
                int kr = c >> 5, n4 = (c & 31) * 4;
                int ok = (bn + n4) < N;
                cp16(&BSN_(s, kr, n4), B + (size_t)(k0 + kr) * ldb + bn + n4, ok);
            }
        }
        cp_commit();
    };

    float acc[4][4][4];
#pragma unroll
    for (int mi = 0; mi < 4; mi++)
#pragma unroll
        for (int ni = 0; ni < 4; ni++)
#pragma unroll
            for (int r = 0; r < 4; r++) acc[mi][ni][r] = 0.f;

    load_stage(0, 0);

    for (int kt = 0; kt < nk; kt++) {
        if (kt + 1 < nk) load_stage((kt + 1) & 1, (kt + 1) * 16);
        if (kt + 1 < nk) cp_wait1(); else cp_wait0();
        __syncthreads();
        int s = kt & 1;

#pragma unroll
        for (int ks = 0; ks < 16; ks += 8) {
            unsigned af[4][4];
#pragma unroll
            for (int mi = 0; mi < 4; mi++) {
                int m0 = wm + mi * 16;
                af[mi][0] = f2tf32(AS_(s, m0 +     qid, ks +     tq));
                af[mi][1] = f2tf32(AS_(s, m0 + 8 + qid, ks +     tq));
                af[mi][2] = f2tf32(AS_(s, m0 +     qid, ks + 4 + tq));
                af[mi][3] = f2tf32(AS_(s, m0 + 8 + qid, ks + 4 + tq));
            }
            unsigned bf[4][2];
#pragma unroll
            for (int ni = 0; ni < 4; ni++) {
                int n0 = wn + ni * 8;
                float g0, g1;
                if (transB) {
                    g0 = BST_(s, n0 + qid, ks +     tq);
                    g1 = BST_(s, n0 + qid, ks + 4 + tq);
                } else {
                    g0 = BSN_(s, ks +     tq, n0 + qid);
                    g1 = BSN_(s, ks + 4 + tq, n0 + qid);
                }
                bf[ni][0] = f2tf32(g0);
                bf[ni][1] = f2tf32(g1);
            }
#pragma unroll
            for (int mi = 0; mi < 4; mi++)
#pragma unroll
                for (int ni = 0; ni < 4; ni++)
                    mma_tf32(acc[mi][ni], af[mi], bf[ni]);
        }
        __syncthreads();
    }

    // ---- epilogue ----
#pragma unroll
    for (int mi = 0; mi < 4; mi++) {
        int r0 = bm + wm + mi * 16 + qid;
#pragma unroll
        for (int ni = 0; ni < 4; ni++) {
            int c0 = bn + wn + ni * 8 + 2 * tq;
#pragma unroll
            for (int e = 0; e < 4; e++) {
                int rr = r0 + (e >> 1) * 8;
                int cc = c0 + (e & 1);
                if (cc >= N) continue;
                float vv = acc[mi][ni][e];
                if (bias)  vv += bias[cc];
                if (resid) vv += resid[(size_t)rr * ldr + cc];
                if (doRelu) vv = fmaxf(vv, 0.f);
                C[(size_t)rr * ldc + cc] = vv;
            }
        }
    }
}

// ---------------- masked softmax with analytic rel-shift, in place over AC ----------------
__global__ __launch_bounds__(256)
void softmax_kernel(float* __restrict__ P, const float* __restrict__ BD)
{
    int i = blockIdx.x, z = blockIdx.y;
    float*       ac = P  + ((size_t)z * Lc + i) * Tc;
    const float* bd = BD + ((size_t)z * Lc + i) * Tc;
    int valid = i + MEMc + 1;
    int shift = Lc - 1 - i;
    __shared__ float red[256];
    int tid = threadIdx.x;

    float mx = -1e30f;
    for (int j = tid; j < valid; j += 256)
        mx = fmaxf(mx, (ac[j] + bd[j + shift]) * SCALEF);
    red[tid] = mx; __syncthreads();
    for (int s = 128; s > 0; s >>= 1) {
        if (tid < s) red[tid] = fmaxf(red[tid], red[tid + s]);
        __syncthreads();
    }
    mx = red[0]; __syncthreads();

    float sum = 0.f;
    for (int j = tid; j < valid; j += 256)
        sum += __expf((ac[j] + bd[j + shift]) * SCALEF - mx);
    red[tid] = sum; __syncthreads();
    for (int s = 128; s > 0; s >>= 1) {
        if (tid < s) red[tid] += red[tid + s];
        __syncthreads();
    }
    float inv = 1.f / red[0];

    for (int j = tid; j < Tc; j += 256) {
        float p = 0.f;
        if (j < valid)
            p = __expf((ac[j] + bd[j + shift]) * SCALEF - mx) * inv;
        ac[j] = p;
    }
}

// ---------------- attn_matrix = mean over (b,h) of prob ----------------
__global__ __launch_bounds__(256)
void attn_reduce_kernel(const float* __restrict__ P, float* __restrict__ attn)
{
    int i = blockIdx.x;
    for (int j = threadIdx.x; j < Tc; j += 256) {
        float s = 0.f;
#pragma unroll
        for (int z = 0; z < Bc*Hc; z++)
            s += P[((size_t)z * Lc + i) * Tc + j];
        attn[(size_t)i * Tc + j] = s * (1.f / (Bc*Hc));
    }
}

// ---------------- layernorm over last dim D ----------------
__global__ __launch_bounds__(256)
void ln_kernel(const float* __restrict__ X, float* __restrict__ Y,
               const float* __restrict__ g, const float* __restrict__ b)
{
    int row = blockIdx.x;
    const float* xr = X + (size_t)row * Dc;
    float*       yr = Y + (size_t)row * Dc;
    __shared__ float r1[256], r2[256];
    int tid = threadIdx.x;
    float s1 = 0.f, s2 = 0.f;
    for (int d = tid; d < Dc; d += 256) {
        float v = xr[d];
        s1 += v; s2 += v*v;
    }
    r1[tid] = s1; r2[tid] = s2; __syncthreads();
    for (int s = 128; s > 0; s >>= 1) {
        if (tid < s) { r1[tid] += r1[tid+s]; r2[tid] += r2[tid+s]; }
        __syncthreads();
    }
    float mean = r1[0] * (1.f/Dc);
    float var  = r2[0] * (1.f/Dc) - mean*mean;
    float rinv = rsqrtf(var + 1e-5f);
    for (int d = tid; d < Dc; d += 256)
        yr[d] = (xr[d] - mean) * rinv * g[d] + b[d];
}

// ---------------- host ----------------
static void launch_gemm(const float* A, const float* B, float* C,
                        int M, int N, int K, int lda, int ldb, int ldc,
                        int Z, int Hdim,
                        long long sAb, long long sAh, long long sBb, long long sBh,
                        long long sCb, long long sCh,
                        const float* bias, const float* resid, int ldr,
                        int doRelu, int transB)
{
    dim3 g((N + 127) / 128, (M + 127) / 128, Z);
    tf32_gemm<<<g, 256>>>(A, B, C, M, N, K, lda, ldb, ldc, Hdim,
                          sAb, sAh, sBb, sBh, sCb, sCh, bias, resid, ldr, doRelu, transB);
}

extern "C" void kernel_launch(void* const* d_in, const int* in_sizes, int n_in,
                              void* d_out, int out_size)
{
    int o = (in_sizes[5] == 1048576) ? 0 : 1;

    const float* x    = (const float*)d_in[0];
    const float* pe   = (const float*)d_in[1];
    const float* pu   = (const float*)d_in[2];
    const float* pv   = (const float*)d_in[3];
    const float* mem  = (const float*)d_in[4];
    const float* Wq   = (const float*)d_in[5  + o];
    const float* Wkv  = (const float*)d_in[6  + o];
    const float* Wo   = (const float*)d_in[7  + o];
    const float* Wrel = (const float*)d_in[8  + o];
    const float* g1   = (const float*)d_in[9  + o];
    const float* b1l  = (const float*)d_in[10 + o];
    const float* W1   = (const float*)d_in[11 + o];
    const float* b1   = (const float*)d_in[12 + o];
    const float* W2   = (const float*)d_in[13 + o];
    const float* b2   = (const float*)d_in[14 + o];
    const float* g2   = (const float*)d_in[15 + o];
    const float* b2l  = (const float*)d_in[16 + o];

    float *p_c, *p_kv, *p_r, *p_q, *p_qu, *p_qv, *p_AC, *p_BD, *p_vec, *p_res, *p_out1, *p_ff1, *p_res2;
    cudaGetSymbolAddress((void**)&p_c,    g_c);
    cudaGetSymbolAddress((void**)&p_kv,   g_kv);
    cudaGetSymbolAddress((void**)&p_r,    g_r);
    cudaGetSymbolAddress((void**)&p_q,    g_q);
    cudaGetSymbolAddress((void**)&p_qu,   g_qu);
    cudaGetSymbolAddress((void**)&p_qv,   g_qv);
    cudaGetSymbolAddress((void**)&p_AC,   g_AC);
    cudaGetSymbolAddress((void**)&p_BD,   g_BD);
    cudaGetSymbolAddress((void**)&p_vec,  g_vec);
    cudaGetSymbolAddress((void**)&p_res,  g_res);
    cudaGetSymbolAddress((void**)&p_out1, g_out1);
    cudaGetSymbolAddress((void**)&p_ff1,  g_ff1);
    cudaGetSymbolAddress((void**)&p_res2, g_res2);

    float* out_main = (float*)d_out;
    float* out_attn = out_main + (size_t)Lc*Bc*Dc;

    // 1) c = concat(memory, x)
    concat_kernel<<<(Tc*Bc*Dc + 255)/256, 256>>>(mem, x, p_c);

    // 2) kv = c @ Wkv
    launch_gemm(p_c, Wkv, p_kv, Tc*Bc, 2*HDc, Dc, Dc, 2*HDc, 2*HDc,
                1, 1, 0,0,0,0,0,0, nullptr, nullptr, 0, 0, 0);
    // 3) r = pos_emb @ Wrel
    launch_gemm(pe, Wrel, p_r, Tc*Bc, HDc, Dc, Dc, HDc, HDc,
                1, 1, 0,0,0,0,0,0, nullptr, nullptr, 0, 0, 0);
    // 4) q = x @ Wq ; then qu = q+u, qv = q+v
    launch_gemm(x, Wq, p_q, Lc*Bc, HDc, Dc, Dc, HDc, HDc,
                1, 1, 0,0,0,0,0,0, nullptr, nullptr, 0, 0, 0);
    qbias_kernel<<<(Lc*Bc*HDc + 255)/256, 256>>>(p_q, pu, pv, p_qu, p_qv);

    // 5) AC = qu @ k^T, BD = qv @ r^T  (batched over z=(b,h), transB)
    launch_gemm(p_qu, p_kv, p_AC, Lc, Tc, DHc, Bc*HDc, Bc*2*HDc, Tc,
                Bc*Hc, Hc,
                (long long)HDc, (long long)DHc,          // A (qu) strides b,h
                (long long)2*HDc, (long long)DHc,        // B (k) strides b,h
                (long long)Hc*Lc*Tc, (long long)Lc*Tc,   // C strides b,h
                nullptr, nullptr, 0, 0, 1);
    launch_gemm(p_qv, p_r, p_BD, Lc, Tc, DHc, Bc*HDc, Bc*HDc, Tc,
                Bc*Hc, Hc,
                (long long)HDc, (long long)DHc,
                (long long)HDc, (long long)DHc,
                (long long)Hc*Lc*Tc, (long long)Lc*Tc,
                nullptr, nullptr, 0, 0, 1);

    // 6) masked softmax (rel-shift folded in)
    softmax_kernel<<<dim3(Lc, Bc*Hc), 256>>>(p_AC, p_BD);

    // 7) attn_matrix
    attn_reduce_kernel<<<Lc, 256>>>(p_AC, out_attn);

    // 8) vec = prob @ v  (batched, B row-major [T, DH] with ldb = B*2*HD)
    launch_gemm(p_AC, p_kv + HDc, p_vec, Lc, DHc, Tc, Tc, Bc*2*HDc, Bc*HDc,
                Bc*Hc, Hc,
                (long long)Hc*Lc*Tc, (long long)Lc*Tc,
                (long long)2*HDc, (long long)DHc,
                (long long)HDc, (long long)DHc,
                nullptr, nullptr, 0, 0, 0);

    // 9) res = x + vec @ Wo
    launch_gemm(p_vec, Wo, p_res, Lc*Bc, Dc, HDc, HDc, Dc, Dc,
                1, 1, 0,0,0,0,0,0, nullptr, x, Dc, 0, 0);

    // 10) out1 = LN1(res)
    ln_kernel<<<Lc*Bc, 256>>>(p_res, p_out1, g1, b1l);

    // 11) ff1 = relu(out1 @ W1 + b1)
    launch_gemm(p_out1, W1, p_ff1, Lc*Bc, DFFc, Dc, Dc, DFFc, DFFc,
                1, 1, 0,0,0,0,0,0, b1, nullptr, 0, 1, 0);

    // 12) res2 = out1 + ff1 @ W2 + b2
    launch_gemm(p_ff1, W2, p_res2, Lc*Bc, Dc, DFFc, DFFc, Dc, Dc,
                1, 1, 0,0,0,0,0,0, b2, p_out1, Dc, 0, 0);

    // 13) out = LN2(res2)
    ln_kernel<<<Lc*Bc, 256>>>(p_res2, out_main, g2, b2l);
}

// round 6
// speedup vs baseline: 3.7723x; 1.3877x over previous
#include <cuda_runtime.h>
#include <cuda_bf16.h>
#include <math.h>

#define Lc   1024
#define Bc   2
#define Dc   1024
#define Hc   16
#define DHc  64
#define DFFc 4096
#define MEMc 1024
#define Tc   2048
#define HDc  (Hc*DHc)          // 1024
#define SCALEF 0.125f

// ---------------- scratch (device globals; no allocation) ----------------
__device__ float g_c   [Tc*Bc*Dc];          // rounded concat(memory, x)
__device__ float g_xr  [Lc*Bc*Dc];          // rounded x (GEMM A)
__device__ float g_per [Tc*Bc*Dc];          // rounded pos_emb (GEMM A)
__device__ float g_kv  [Tc*Bc*2*HDc];       // rounded kv proj
__device__ float g_r   [Tc*Bc*HDc];         // rounded rel proj
__device__ float g_qu  [Lc*Bc*HDc];         // rounded q + u
__device__ float g_qv  [Lc*Bc*HDc];         // rounded q + v
__device__ float g_AC  [67108864];          // [B*H, L, T] AC scores, then rounded probs
__device__ float g_BD  [67108864];          // [B*H, L, T] BD scores (unshifted)
__device__ float g_vec [Lc*Bc*HDc];         // rounded attention vec
__device__ float g_res [Lc*Bc*Dc];          // x + attn_out (full precision)
__device__ float g_out1[Lc*Bc*Dc];          // ln1 out (full precision, residual)
__device__ float g_o1r [Lc*Bc*Dc];          // ln1 out rounded (GEMM A)
__device__ float g_ff1 [Lc*Bc*DFFc];        // rounded relu(out1@W1+b1)
__device__ float g_res2[Lc*Bc*Dc];          // out1 + ff (full precision)
// rounded transposed weights
__device__ float g_WkvT[2*HDc*Dc];
__device__ float g_WrelT[HDc*Dc];
__device__ float g_WqT [HDc*Dc];
__device__ float g_WoT [Dc*HDc];
__device__ float g_W1T [DFFc*Dc];
__device__ float g_W2T [Dc*DFFc];
__device__ float g_vt  [Bc*Hc*DHc*Tc];      // v transposed: [b,h,d,t] (already rounded)

// ---------------- helpers ----------------
__device__ __forceinline__ float rnd_tf32(float f) {
    unsigned u;
    asm("cvt.rna.tf32.f32 %0, %1;" : "=r"(u) : "f"(f));
    return __uint_as_float(u);
}
__device__ __forceinline__ void mma_tf32(float c[4], const unsigned a[4], const unsigned b[2]) {
    asm volatile(
        "mma.sync.aligned.m16n8k8.row.col.f32.tf32.tf32.f32 "
        "{%0,%1,%2,%3}, {%4,%5,%6,%7}, {%8,%9}, {%0,%1,%2,%3};"
        : "+f"(c[0]), "+f"(c[1]), "+f"(c[2]), "+f"(c[3])
        : "r"(a[0]), "r"(a[1]), "r"(a[2]), "r"(a[3]), "r"(b[0]), "r"(b[1]));
}
__device__ __forceinline__ void cp16(void* smem, const void* gmem) {
    unsigned s = (unsigned)__cvta_generic_to_shared(smem);
    asm volatile("cp.async.ca.shared.global [%0], [%1], 16;" :: "r"(s), "l"(gmem));
}

// ---------------- elementwise producers (all round their GEMM-feeding outputs) ----------------
__global__ void concat_kernel(const float* __restrict__ mem, const float* __restrict__ x,
                              float* __restrict__ c) {
    int idx = blockIdx.x * 256 + threadIdx.x;
    if (idx < Tc*Bc*Dc)
        c[idx] = rnd_tf32((idx < MEMc*Bc*Dc) ? mem[idx] : x[idx - MEMc*Bc*Dc]);
}

__global__ void round_copy_kernel(const float* __restrict__ in, float* __restrict__ out, int n) {
    int idx = blockIdx.x * 256 + threadIdx.x;
    if (idx < n) out[idx] = rnd_tf32(in[idx]);
}

// out[n][k] = rnd(in[k][n]); grid (N/32, K/32), block (32,8)
__global__ void transpose_kernel(const float* __restrict__ in, float* __restrict__ out,
                                 int K, int N) {
    __shared__ float t[32][33];
    int n0 = blockIdx.x * 32, k0 = blockIdx.y * 32;
    int tx = threadIdx.x, ty = threadIdx.y;
    for (int r = ty; r < 32; r += 8)
        t[r][tx] = in[(size_t)(k0 + r) * N + n0 + tx];
    __syncthreads();
    for (int r = ty; r < 32; r += 8)
        out[(size_t)(n0 + r) * K + k0 + tx] = rnd_tf32(t[tx][r]);
}

// vt[b,h,d,t] = v[t,b,h,d] (kv already rounded); grid (T/32, DH/32, B*H)
__global__ void vtrans_kernel(const float* __restrict__ kv, float* __restrict__ vt) {
    __shared__ float t[32][33];
    int b = blockIdx.z >> 4;
    int j0 = blockIdx.x * 32, d0 = blockIdx.y * 32;
    int tx = threadIdx.x, ty = threadIdx.y;
    int h = blockIdx.z & 15;
    const float* in = kv + b * (2*HDc) + HDc + h * DHc;
    for (int r = ty; r < 32; r += 8)
        t[r][tx] = in[(size_t)(j0 + r) * (Bc*2*HDc) + d0 + tx];
    __syncthreads();
    float* out = vt + (size_t)blockIdx.z * DHc * Tc;
    for (int r = ty; r < 32; r += 8)
        out[(size_t)(d0 + r) * Tc + j0 + tx] = t[tx][r];
}

// ---------------- TF32 tensor-core GEMM (mma.sync, pre-rounded operands) ----------------
// D[m][n] = sum_k A[m][k]*Bt[n][k]  (both K-major, already tf32-rounded).
// M % 128 == 0, N % BN == 0, K % 32 == 0. BK=32, 2-stage cp.async, XOR-swizzled smem.
template<int BN>
__global__ __launch_bounds__(256, 2)
void tf32_gemm(const float* __restrict__ A, const float* __restrict__ Bt,
               float* __restrict__ C,
               int M, int N, int K, int lda, int ldb, int ldc,
               int Hdim, long long sAb, long long sAh, long long sBb, long long sBh,
               long long sCb, long long sCh,
               const float* __restrict__ bias, const float* __restrict__ resid,
               int ldr, int doRelu, int roundOut,
               float* __restrict__ C2, const float* __restrict__ bias2)
{
    constexpr int NT = BN / 32;            // n-tiles (of 8) per warp
    extern __shared__ float sm[];
    float* As = sm;                        // [2][128*32], swizzled
    float* Bs = sm + 2 * 128 * 32;         // [2][BN*32], swizzled

    int z = blockIdx.z, bz = z / Hdim, hz = z % Hdim;
    A  += bz * sAb + hz * sAh;
    Bt += bz * sBb + hz * sBh;
    C  += bz * sCb + hz * sCh;

    int tid = threadIdx.x, warp = tid >> 5, lane = tid & 31;
    int qid = lane >> 2, tq = lane & 3;
    int wm = (warp >> 2) * 64;
    int wn = (warp & 3) * (NT * 8);
    int bm = blockIdx.y * 128, bn = blockIdx.x * BN;

    auto load_stage = [&](int st, int k0) {
        float* as = As + st * 4096;
#pragma unroll
        for (int i = 0; i < 4; i++) {
            int idx = tid + i * 256;               // 0..1023
            int row = idx >> 3, c = idx & 7;
            cp16(as + row * 32 + ((c ^ (row & 7)) << 2),
                 A + (size_t)(bm + row) * lda + k0 + c * 4);
        }
        float* bs = Bs + st * BN * 32;
#pragma unroll
        for (int i = 0; i < BN / 32; i++) {
            int idx = tid + i * 256;
            int row = idx >> 3, c = idx & 7;
            cp16(bs + row * 32 + ((c ^ (row & 7)) << 2),
                 Bt + (size_t)(bn + row) * ldb + k0 + c * 4);
        }
        asm volatile("cp.async.commit_group;");
    };

    float acc[4][NT][4];
#pragma unroll
    for (int mi = 0; mi < 4; mi++)
#pragma unroll
        for (int ni = 0; ni < NT; ni++)
#pragma unroll
            for (int e = 0; e < 4; e++) acc[mi][ni][e] = 0.f;

    int KT = K >> 5;
    load_stage(0, 0);

    for (int kt = 0; kt < KT; kt++) {
        if (kt + 1 < KT) {
            load_stage((kt + 1) & 1, (kt + 1) * 32);
            asm volatile("cp.async.wait_group 1;");
        } else {
            asm volatile("cp.async.wait_group 0;");
        }
        __syncthreads();
        const float* as = As + (kt & 1) * 4096;
        const float* bs = Bs + (kt & 1) * BN * 32;

#pragma unroll
        for (int s8 = 0; s8 < 4; s8++) {
            int xa = (((s8 << 1)    ) ^ qid) << 2;
            int xb = (((s8 << 1) + 1) ^ qid) << 2;
            unsigned af[4][4];
#pragma unroll
            for (int mi = 0; mi < 4; mi++) {
                int base = (wm + mi * 16 + qid) * 32 + tq;
                af[mi][0] = __float_as_uint(as[base +       xa]);
                af[mi][1] = __float_as_uint(as[base + 256 + xa]);
                af[mi][2] = __float_as_uint(as[base +       xb]);
                af[mi][3] = __float_as_uint(as[base + 256 + xb]);
            }
            unsigned bf[NT][2];
#pragma unroll
            for (int ni = 0; ni < NT; ni++) {
                int base = (wn + ni * 8 + qid) * 32 + tq;
                bf[ni][0] = __float_as_uint(bs[base + xa]);
                bf[ni][1] = __float_as_uint(bs[base + xb]);
            }
#pragma unroll
            for (int mi = 0; mi < 4; mi++)
#pragma unroll
                for (int ni = 0; ni < NT; ni++)
                    mma_tf32(acc[mi][ni], af[mi], bf[ni]);
        }
        __syncthreads();
    }

    // ---- epilogue: float2 stores, optional bias/resid/relu/round + dual output ----
#pragma unroll
    for (int mi = 0; mi < 4; mi++) {
        int r0 = bm + wm + mi * 16 + qid;
#pragma unroll
        for (int ni = 0; ni < NT; ni++) {
            int c0 = bn + wn + ni * 8 + 2 * tq;
#pragma unroll
            for (int h = 0; h < 2; h++) {
                int rr = r0 + h * 8;
                float vx = acc[mi][ni][2*h], vy = acc[mi][ni][2*h+1];
                float ax = vx, ay = vy;
                if (bias)  { vx += bias[c0]; vy += bias[c0+1]; }
                if (resid) {
                    const float* rp = resid + (size_t)rr * ldr + c0;
                    vx += rp[0]; vy += rp[1];
                }
                if (doRelu) { vx = fmaxf(vx, 0.f); vy = fmaxf(vy, 0.f); }
                if (roundOut) { vx = rnd_tf32(vx); vy = rnd_tf32(vy); }
                *(float2*)(C + (size_t)rr * ldc + c0) = make_float2(vx, vy);
                if (C2) {
                    float wx = rnd_tf32(ax + bias2[c0]);
                    float wy = rnd_tf32(ay + bias2[c0+1]);
                    *(float2*)(C2 + (size_t)rr * ldc + c0) = make_float2(wx, wy);
                }
            }
        }
    }
}

// ---------------- register-resident masked softmax (rel-shift folded), rounded probs ----------------
__global__ __launch_bounds__(256)
void softmax_kernel(float* __restrict__ P, const float* __restrict__ BD)
{
    int i = blockIdx.x, z = blockIdx.y, tid = threadIdx.x;
    float*       ac = P  + ((size_t)z * Lc + i) * Tc;
    const float* bd = BD + ((size_t)z * Lc + i) * Tc;
    int valid = i + MEMc + 1;
    int shift = Lc - 1 - i;

    float s[8];
    float mx = -1e30f;
#pragma unroll
    for (int t = 0; t < 8; t++) {
        int j = tid + 256 * t;
        if (j < valid) {
            s[t] = (ac[j] + bd[j + shift]) * SCALEF;
            mx = fmaxf(mx, s[t]);
        } else s[t] = -1e30f;
    }
    __shared__ float red[8], red2[8];
    for (int o = 16; o > 0; o >>= 1) mx = fmaxf(mx, __shfl_xor_sync(~0u, mx, o));
    if ((tid & 31) == 0) red[tid >> 5] = mx;
    __syncthreads();
    mx = red[0];
#pragma unroll
    for (int w = 1; w < 8; w++) mx = fmaxf(mx, red[w]);

    float sum = 0.f;
#pragma unroll
    for (int t = 0; t < 8; t++) {
        float e = (s[t] > -1e29f) ? __expf(s[t] - mx) : 0.f;
        s[t] = e; sum += e;
    }
    for (int o = 16; o > 0; o >>= 1) sum += __shfl_xor_sync(~0u, sum, o);
    if ((tid & 31) == 0) red2[tid >> 5] = sum;
    __syncthreads();
    sum = 0.f;
#pragma unroll
    for (int w = 0; w < 8; w++) sum += red2[w];
    float inv = 1.f / sum;
#pragma unroll
    for (int t = 0; t < 8; t++)
        ac[tid + 256 * t] = rnd_tf32(s[t] * inv);
}

// ---------------- attn_matrix = mean over (b,h) of prob ----------------
__global__ __launch_bounds__(256)
void attn_reduce_kernel(const float* __restrict__ P, float* __restrict__ attn)
{
    int i = blockIdx.x;
    for (int j = threadIdx.x; j < Tc; j += 256) {
        float s = 0.f;
#pragma unroll
        for (int z = 0; z < Bc*Hc; z++)
            s += P[((size_t)z * Lc + i) * Tc + j];
        attn[(size_t)i * Tc + j] = s * (1.f / (Bc*Hc));
    }
}

// ---------------- layernorm (optional rounded second output) ----------------
__global__ __launch_bounds__(256)
void ln_kernel(const float* __restrict__ X, float* __restrict__ Y, float* __restrict__ Yr,
               const float* __restrict__ g, const float* __restrict__ b)
{
    int row = blockIdx.x;
    const float* xr = X + (size_t)row * Dc;
    float*       yr = Y + (size_t)row * Dc;
    __shared__ float r1[256], r2[256];
    int tid = threadIdx.x;
    float s1 = 0.f, s2 = 0.f;
    for (int d = tid; d < Dc; d += 256) {
        float v = xr[d];
        s1 += v; s2 += v*v;
    }
    r1[tid] = s1; r2[tid] = s2; __syncthreads();
    for (int s = 128; s > 0; s >>= 1) {
        if (tid < s) { r1[tid] += r1[tid+s]; r2[tid] += r2[tid+s]; }
        __syncthreads();
    }
    float mean = r1[0] * (1.f/Dc);
    float var  = r2[0] * (1.f/Dc) - mean*mean;
    float rinv = rsqrtf(var + 1e-5f);
    for (int d = tid; d < Dc; d += 256) {
        float v = (xr[d] - mean) * rinv * g[d] + b[d];
        yr[d] = v;
        if (Yr) Yr[(size_t)row * Dc + d] = rnd_tf32(v);
    }
}

// ---------------- host ----------------
template<int BN>
static void tcg(const float* A, const float* Bt, float* C,
                int M, int N, int K, int lda, int ldb, int ldc,
                int Z, int Hdim,
                long long sAb, long long sAh, long long sBb, long long sBh,
                long long sCb, long long sCh,
                const float* bias, const float* resid, int ldr, int doRelu, int roundOut,
                float* C2 = nullptr, const float* bias2 = nullptr)
{
    size_t smB = (size_t)(2*128*32 + 2*BN*32) * 4;
    dim3 g(N / BN, M / 128, Z);
    tf32_gemm<BN><<<g, 256, smB>>>(A, Bt, C, M, N, K, lda, ldb, ldc, Hdim,
                                   sAb, sAh, sBb, sBh, sCb, sCh,
                                   bias, resid, ldr, doRelu, roundOut, C2, bias2);
}

extern "C" void kernel_launch(void* const* d_in, const int* in_sizes, int n_in,
                              void* d_out, int out_size)
{
    int o = (in_sizes[5] == 1048576) ? 0 : 1;

    const float* x    = (const float*)d_in[0];
    const float* pe   = (const float*)d_in[1];
    const float* pu   = (const float*)d_in[2];
    const float* pv   = (const float*)d_in[3];
    const float* mem  = (const float*)d_in[4];
    const float* Wq   = (const float*)d_in[5  + o];
    const float* Wkv  = (const float*)d_in[6  + o];
    const float* Wo   = (const float*)d_in[7  + o];
    const float* Wrel = (const float*)d_in[8  + o];
    const float* g1   = (const float*)d_in[9  + o];
    const float* b1l  = (const float*)d_in[10 + o];
    const float* W1   = (const float*)d_in[11 + o];
    const float* b1   = (const float*)d_in[12 + o];
    const float* W2   = (const float*)d_in[13 + o];
    const float* b2   = (const float*)d_in[14 + o];
    const float* g2   = (const float*)d_in[15 + o];
    const float* b2l  = (const float*)d_in[16 + o];

    float *p_c, *p_xr, *p_per, *p_kv, *p_r, *p_qu, *p_qv, *p_AC, *p_BD, *p_vec,
          *p_res, *p_out1, *p_o1r, *p_ff1, *p_res2,
          *p_WkvT, *p_WrelT, *p_WqT, *p_WoT, *p_W1T, *p_W2T, *p_vt;
    cudaGetSymbolAddress((void**)&p_c,    g_c);
    cudaGetSymbolAddress((void**)&p_xr,   g_xr);
    cudaGetSymbolAddress((void**)&p_per,  g_per);
    cudaGetSymbolAddress((void**)&p_kv,   g_kv);
    cudaGetSymbolAddress((void**)&p_r,    g_r);
    cudaGetSymbolAddress((void**)&p_qu,   g_qu);
    cudaGetSymbolAddress((void**)&p_qv,   g_qv);
    cudaGetSymbolAddress((void**)&p_AC,   g_AC);
    cudaGetSymbolAddress((void**)&p_BD,   g_BD);
    cudaGetSymbolAddress((void**)&p_vec,  g_vec);
    cudaGetSymbolAddress((void**)&p_res,  g_res);
    cudaGetSymbolAddress((void**)&p_out1, g_out1);
    cudaGetSymbolAddress((void**)&p_o1r,  g_o1r);
    cudaGetSymbolAddress((void**)&p_ff1,  g_ff1);
    cudaGetSymbolAddress((void**)&p_res2, g_res2);
    cudaGetSymbolAddress((void**)&p_WkvT, g_WkvT);
    cudaGetSymbolAddress((void**)&p_WrelT,g_WrelT);
    cudaGetSymbolAddress((void**)&p_WqT,  g_WqT);
    cudaGetSymbolAddress((void**)&p_WoT,  g_WoT);
    cudaGetSymbolAddress((void**)&p_W1T,  g_W1T);
    cudaGetSymbolAddress((void**)&p_W2T,  g_W2T);
    cudaGetSymbolAddress((void**)&p_vt,   g_vt);

    cudaFuncSetAttribute(tf32_gemm<128>, cudaFuncAttributeMaxDynamicSharedMemorySize,
                         (2*128*32 + 2*128*32) * 4);
    cudaFuncSetAttribute(tf32_gemm<64>,  cudaFuncAttributeMaxDynamicSharedMemorySize,
                         (2*128*32 + 2*64*32) * 4);

    float* out_main = (float*)d_out;
    float* out_attn = out_main + (size_t)Lc*Bc*Dc;

    dim3 tb(32, 8);

    // 0) producers: rounded concat / copies / weight transposes
    concat_kernel<<<(Tc*Bc*Dc + 255)/256, 256>>>(mem, x, p_c);
    round_copy_kernel<<<(Lc*Bc*Dc + 255)/256, 256>>>(x,  p_xr,  Lc*Bc*Dc);
    round_copy_kernel<<<(Tc*Bc*Dc + 255)/256, 256>>>(pe, p_per, Tc*Bc*Dc);
    transpose_kernel<<<dim3(2*HDc/32, Dc/32),  tb>>>(Wkv,  p_WkvT,  Dc, 2*HDc);
    transpose_kernel<<<dim3(HDc/32,   Dc/32),  tb>>>(Wrel, p_WrelT, Dc, HDc);
    transpose_kernel<<<dim3(HDc/32,   Dc/32),  tb>>>(Wq,   p_WqT,   Dc, HDc);
    transpose_kernel<<<dim3(Dc/32,    HDc/32), tb>>>(Wo,   p_WoT,   HDc, Dc);
    transpose_kernel<<<dim3(DFFc/32,  Dc/32),  tb>>>(W1,   p_W1T,   Dc, DFFc);
    transpose_kernel<<<dim3(Dc/32,    DFFc/32),tb>>>(W2,   p_W2T,   DFFc, Dc);

    // 1) kv = c @ Wkv  (rounded out)
    tcg<128>(p_c, p_WkvT, p_kv, Tc*Bc, 2*HDc, Dc, Dc, Dc, 2*HDc,
             1, 1, 0,0,0,0,0,0, nullptr, nullptr, 0, 0, 1);
    // 2) r = pos_emb @ Wrel (rounded out)
    tcg<128>(p_per, p_WrelT, p_r, Tc*Bc, HDc, Dc, Dc, Dc, HDc,
             1, 1, 0,0,0,0,0,0, nullptr, nullptr, 0, 0, 1);
    // 3) qu = x@Wq + u ; qv = x@Wq + v  (dual rounded outputs)
    tcg<128>(p_xr, p_WqT, p_qu, Lc*Bc, HDc, Dc, Dc, Dc, HDc,
             1, 1, 0,0,0,0,0,0, pu, nullptr, 0, 0, 1, p_qv, pv);

    // v transpose (kv already rounded)
    vtrans_kernel<<<dim3(Tc/32, DHc/32, Bc*Hc), tb>>>(p_kv, p_vt);

    // 4) AC = qu @ k^T ; BD = qv @ r^T  (batched, full-precision scores)
    tcg<128>(p_qu, p_kv, p_AC, Lc, Tc, DHc, Bc*HDc, Bc*2*HDc, Tc,
             Bc*Hc, Hc,
             (long long)HDc, (long long)DHc,
             (long long)2*HDc, (long long)DHc,
             (long long)Hc*Lc*Tc, (long long)Lc*Tc,
             nullptr, nullptr, 0, 0, 0);
    tcg<128>(p_qv, p_r, p_BD, Lc, Tc, DHc, Bc*HDc, Bc*HDc, Tc,
             Bc*Hc, Hc,
             (long long)HDc, (long long)DHc,
             (long long)HDc, (long long)DHc,
             (long long)Hc*Lc*Tc, (long long)Lc*Tc,
             nullptr, nullptr, 0, 0, 0);

    // 5) softmax (rounds probs) + attn matrix
    softmax_kernel<<<dim3(Lc, Bc*Hc), 256>>>(p_AC, p_BD);
    attn_reduce_kernel<<<Lc, 256>>>(p_AC, out_attn);

    // 6) vec = prob @ v  (BN=64 tile, rounded out)
    tcg<64>(p_AC, p_vt, p_vec, Lc, DHc, Tc, Tc, Tc, Bc*HDc,
            Bc*Hc, Hc,
            (long long)Hc*Lc*Tc, (long long)Lc*Tc,
            (long long)Hc*DHc*Tc, (long long)DHc*Tc,
            (long long)HDc, (long long)DHc,
            nullptr, nullptr, 0, 0, 1);

    // 7) res = x + vec @ Wo  (full precision out)
    tcg<128>(p_vec, p_WoT, p_res, Lc*Bc, Dc, HDc, HDc, HDc, Dc,
             1, 1, 0,0,0,0,0,0, nullptr, x, Dc, 0, 0);

    // 8) LN1 (full + rounded outputs)
    ln_kernel<<<Lc*Bc, 256>>>(p_res, p_out1, p_o1r, g1, b1l);

    // 9) ff1 = relu(out1 @ W1 + b1) (rounded out)
    tcg<128>(p_o1r, p_W1T, p_ff1, Lc*Bc, DFFc, Dc, Dc, Dc, DFFc,
             1, 1, 0,0,0,0,0,0, b1, nullptr, 0, 1, 1);

    // 10) res2 = out1 + ff1 @ W2 + b2 (full precision out)
    tcg<128>(p_ff1, p_W2T, p_res2, Lc*Bc, Dc, DFFc, DFFc, DFFc, Dc,
             1, 1, 0,0,0,0,0,0, b2, p_out1, Dc, 0, 0);

    // 11) LN2 -> final output
    ln_kernel<<<Lc*Bc, 256>>>(p_res2, out_main, nullptr, g2, b2l);
}